// round 12
// baseline (speedup 1.0000x reference)
#include <cuda_runtime.h>
#include <cuda_fp16.h>
#include <stdint.h>

#define THREADS 256          // 8 warps -> 2 per SMSP, full 255-reg budget
#define D_IN 64
#define PERSIST_BLOCKS 148   // 1 CTA per SM

// ---- smem byte offsets: LDSM-tiled weights (8n x 8k fp16 tiles, 16B rows) ----
#define W1_B  0          // 32 blocks x 512B = 16384
#define W2_B  16384      // 32 blocks x 512B = 16384
#define W3_B  32768      // 4 blocks x 512B = 2048
#define B1_B  34816      // half2-packed biases: 64 x u32
#define B2_B  35072      // 32 x u32
#define B3_B  35200      // f32[16]
#define W4_B  35264      // f32[16]
#define SMEM_BYTES 35328

__device__ float g_logits[1 << 20];

// ---- helpers ----
__device__ __forceinline__ uint32_t smem_u32(const void* p) {
    uint32_t a;
    asm("{ .reg .u64 t; cvta.to.shared.u64 t, %1; cvt.u32.u64 %0, t; }" : "=r"(a) : "l"(p));
    return a;
}
__device__ __forceinline__ void mma16816(float* c, const uint32_t* a, uint32_t b0, uint32_t b1) {
    asm volatile(
        "mma.sync.aligned.m16n8k16.row.col.f32.f16.f16.f32 "
        "{%0,%1,%2,%3}, {%4,%5,%6,%7}, {%8,%9}, {%0,%1,%2,%3};"
        : "+f"(c[0]), "+f"(c[1]), "+f"(c[2]), "+f"(c[3])
        : "r"(a[0]), "r"(a[1]), "r"(a[2]), "r"(a[3]), "r"(b0), "r"(b1));
}
__device__ __forceinline__ void ldsm4(uint32_t* d, uint32_t addr) {
    asm volatile("ldmatrix.sync.aligned.m8n8.x4.shared.b16 {%0,%1,%2,%3}, [%4];"
        : "=r"(d[0]), "=r"(d[1]), "=r"(d[2]), "=r"(d[3]) : "r"(addr));
}
__device__ __forceinline__ void prefetchL2(const void* p) {
    asm volatile("prefetch.global.L2 [%0];" :: "l"(p));
}
__device__ __forceinline__ uint32_t packh2(float a, float b) {
    __half2 h = __floats2half2_rn(a, b);
    return *(uint32_t*)&h;
}
__device__ __forceinline__ uint32_t pkf2(float lo, float hi) {
    uint32_t r;
    asm("cvt.rn.f16x2.f32 %0, %1, %2;" : "=r"(r) : "f"(hi), "f"(lo));
    return r;
}
// epilogue: tanh(acc + bias) in fp16x2; output word IS the next A-fragment
__device__ __forceinline__ uint32_t tanh2_b(float c0, float c1, uint32_t bias2) {
    uint32_t p = pkf2(c0, c1);
    uint32_t s;
    asm("add.rn.f16x2 %0, %1, %2;" : "=r"(s) : "r"(p), "r"(bias2));
    uint32_t r;
    asm("tanh.approx.f16x2 %0, %1;" : "=r"(r) : "r"(s));
    return r;
}
__device__ __forceinline__ float tanh_b(float acc, float b) {
    float s = acc + b;
    float r; asm("tanh.approx.f32 %0, %1;" : "=f"(r) : "f"(s));
    return r;
}

// ---------------------------------------------------------------------------
// Persistent fused MLP, 32 tokens per warp per unit, zero loop barriers.
// KEY CHANGE (r12): double-buffered accumulators in layers 1 & 2 so the
// epilogue (MUFU/fma) of group jp-1 is scoreboard-independent of group jp's
// MMAs -> tensor pipe keeps issuing while tanh runs (phases overlap instead
// of serializing).
// ---------------------------------------------------------------------------
__global__ void __launch_bounds__(THREADS, 1)
mlp_hmma_kernel(const float* __restrict__ x, int nunits,
                const float* __restrict__ W1, const float* __restrict__ b1,
                const float* __restrict__ W2, const float* __restrict__ b2,
                const float* __restrict__ W3, const float* __restrict__ b3,
                const float* __restrict__ W4, const float* __restrict__ b4) {
    extern __shared__ char smem[];
    uint32_t* sB1 = (uint32_t*)(smem + B1_B);   // half2-packed
    uint32_t* sB2 = (uint32_t*)(smem + B2_B);   // half2-packed
    float* sB3 = (float*)(smem + B3_B);
    float* sW4 = (float*)(smem + W4_B);

    const int tid = threadIdx.x;

    // ---- stage weights once into LDSM tile layout (single fp16) ----
    for (int i = tid; i < 8192; i += THREADS) {   // W1: [64k x 128n]
        int k = i >> 7, n = i & 127;
        __half h = __float2half_rn(W1[i]);
        int kk = k >> 4, khalf = (k >> 3) & 1, kin = k & 7;
        int jp = n >> 4, j01 = (n >> 3) & 1, nin = n & 7;
        uint32_t off = ((((jp << 2) + kk) * 4 + j01 * 2 + khalf) << 7) + (nin << 4) + (kin << 1);
        *(__half*)(smem + W1_B + off) = h;
    }
    for (int i = tid; i < 8192; i += THREADS) {   // W2: [128k x 64n]
        int k = i >> 6, n = i & 63;
        __half h = __float2half_rn(W2[i]);
        int kk = k >> 4, khalf = (k >> 3) & 1, kin = k & 7;
        int jp = n >> 4, j01 = (n >> 3) & 1, nin = n & 7;
        uint32_t off = ((((jp << 3) + kk) * 4 + j01 * 2 + khalf) << 7) + (nin << 4) + (kin << 1);
        *(__half*)(smem + W2_B + off) = h;
    }
    for (int i = tid; i < 1024; i += THREADS) {   // W3: [64k x 16n]
        int k = i >> 4, n = i & 15;
        __half h = __float2half_rn(W3[i]);
        int kk = k >> 4, khalf = (k >> 3) & 1, kin = k & 7;
        int j01 = (n >> 3) & 1, nin = n & 7;
        uint32_t off = (((kk << 2) + j01 * 2 + khalf) << 7) + (nin << 4) + (kin << 1);
        *(__half*)(smem + W3_B + off) = h;
    }
    if (tid < 64) sB1[tid] = packh2(b1[2 * tid], b1[2 * tid + 1]);
    else if (tid >= 64 && tid < 96) sB2[tid - 64] = packh2(b2[2 * (tid - 64)], b2[2 * (tid - 64) + 1]);
    else if (tid >= 96 && tid < 112) { sB3[tid - 96] = b3[tid - 96]; sW4[tid - 96] = W4[tid - 96]; }
    __syncthreads();

    const int wid = tid >> 5, lid = tid & 31;
    const int g  = lid >> 2;        // group row 0..7
    const int q  = lid & 3;         // quad col 0..3
    const float bb4 = b4[0];

    const uint32_t smb = smem_u32(smem);
    const uint32_t lane16 = (uint32_t)lid << 4;
    const uint32_t w1 = smb + W1_B + lane16;
    const uint32_t w2 = smb + W2_B + lane16;
    const uint32_t w3 = smb + W3_B + lane16;

    const int nwarps = gridDim.x * (THREADS / 32);
    // -------- persistent unit loop: 32 tokens per warp per iteration --------
    for (int u = blockIdx.x * (THREADS / 32) + wid; u < nunits; u += nwarps) {
        const long long base = (long long)u << 5;
        const float* xw = x + base * D_IN;

        // ---- A1 fragments straight from gmem (fp16), 2 m16 tiles ----
        uint32_t a1[2][4][4];
#pragma unroll
        for (int t = 0; t < 2; t++) {
            const float* xt = xw + t * 16 * D_IN;
#pragma unroll
            for (int kk = 0; kk < 4; kk++) {
                int c0 = q * 2 + 16 * kk;
                float2 p00 = *(const float2*)&xt[g * D_IN + c0];
                float2 p10 = *(const float2*)&xt[(g + 8) * D_IN + c0];
                float2 p01 = *(const float2*)&xt[g * D_IN + c0 + 8];
                float2 p11 = *(const float2*)&xt[(g + 8) * D_IN + c0 + 8];
                a1[t][kk][0] = packh2(p00.x, p00.y);
                a1[t][kk][1] = packh2(p10.x, p10.y);
                a1[t][kk][2] = packh2(p01.x, p01.y);
                a1[t][kk][3] = packh2(p11.x, p11.y);
            }
        }

        // ---- prefetch next unit's X rows into L2 ----
        {
            int nu = u + nwarps;
            if (nu < nunits) {
                const float* nx = x + ((long long)nu << 5) * D_IN;
                prefetchL2(&nx[g * D_IN + q * 16]);
                prefetchL2(&nx[(g + 8) * D_IN + q * 16]);
                prefetchL2(&nx[(g + 16) * D_IN + q * 16]);
                prefetchL2(&nx[(g + 24) * D_IN + q * 16]);
            }
        }

        // ======== Layer 1: [32x64] @ [64x128], acc double-buffered ========
        uint32_t a2[2][8][4];
        float acc[2][2][8];   // [buf][t][8]
#pragma unroll
        for (int jp = 0; jp < 8; jp++) {
            const int cb = jp & 1;
#pragma unroll
            for (int t = 0; t < 2; t++)
#pragma unroll
                for (int i = 0; i < 8; i++) acc[cb][t][i] = 0.f;
#pragma unroll
            for (int kk = 0; kk < 4; kk++) {
                uint32_t bh[4];
                ldsm4(bh, w1 + (uint32_t)(jp * 2048 + kk * 512));
                mma16816(&acc[cb][0][0], a1[0][kk], bh[0], bh[1]);
                mma16816(&acc[cb][0][4], a1[0][kk], bh[2], bh[3]);
                mma16816(&acc[cb][1][0], a1[1][kk], bh[0], bh[1]);
                mma16816(&acc[cb][1][4], a1[1][kk], bh[2], bh[3]);
            }
            if (jp > 0) {   // epilogue of jp-1 overlaps jp's MMAs
                const int ob = cb ^ 1, oj = jp - 1;
                uint32_t bA = sB1[8 * oj + q];
                uint32_t bB = sB1[8 * oj + 4 + q];
#pragma unroll
                for (int t = 0; t < 2; t++) {
                    a2[t][oj][0] = tanh2_b(acc[ob][t][0], acc[ob][t][1], bA);
                    a2[t][oj][1] = tanh2_b(acc[ob][t][2], acc[ob][t][3], bA);
                    a2[t][oj][2] = tanh2_b(acc[ob][t][4], acc[ob][t][5], bB);
                    a2[t][oj][3] = tanh2_b(acc[ob][t][6], acc[ob][t][7], bB);
                }
            }
        }
        {   // final L1 epilogue (jp=7, buf 1)
            uint32_t bA = sB1[8 * 7 + q];
            uint32_t bB = sB1[8 * 7 + 4 + q];
#pragma unroll
            for (int t = 0; t < 2; t++) {
                a2[t][7][0] = tanh2_b(acc[1][t][0], acc[1][t][1], bA);
                a2[t][7][1] = tanh2_b(acc[1][t][2], acc[1][t][3], bA);
                a2[t][7][2] = tanh2_b(acc[1][t][4], acc[1][t][5], bB);
                a2[t][7][3] = tanh2_b(acc[1][t][6], acc[1][t][7], bB);
            }
        }

        // ======== Layer 2: [32x128] @ [128x64], acc double-buffered ========
        uint32_t a3[2][4][4];
#pragma unroll
        for (int jp = 0; jp < 4; jp++) {
            const int cb = jp & 1;
#pragma unroll
            for (int t = 0; t < 2; t++)
#pragma unroll
                for (int i = 0; i < 8; i++) acc[cb][t][i] = 0.f;
#pragma unroll
            for (int kk = 0; kk < 8; kk++) {
                uint32_t bh[4];
                ldsm4(bh, w2 + (uint32_t)(jp * 4096 + kk * 512));
                mma16816(&acc[cb][0][0], a2[0][kk], bh[0], bh[1]);
                mma16816(&acc[cb][0][4], a2[0][kk], bh[2], bh[3]);
                mma16816(&acc[cb][1][0], a2[1][kk], bh[0], bh[1]);
                mma16816(&acc[cb][1][4], a2[1][kk], bh[2], bh[3]);
            }
            if (jp > 0) {
                const int ob = cb ^ 1, oj = jp - 1;
                uint32_t bA = sB2[8 * oj + q];
                uint32_t bB = sB2[8 * oj + 4 + q];
#pragma unroll
                for (int t = 0; t < 2; t++) {
                    a3[t][oj][0] = tanh2_b(acc[ob][t][0], acc[ob][t][1], bA);
                    a3[t][oj][1] = tanh2_b(acc[ob][t][2], acc[ob][t][3], bA);
                    a3[t][oj][2] = tanh2_b(acc[ob][t][4], acc[ob][t][5], bB);
                    a3[t][oj][3] = tanh2_b(acc[ob][t][6], acc[ob][t][7], bB);
                }
            }
        }
        {   // final L2 epilogue (jp=3, buf 1)
            uint32_t bA = sB2[8 * 3 + q];
            uint32_t bB = sB2[8 * 3 + 4 + q];
#pragma unroll
            for (int t = 0; t < 2; t++) {
                a3[t][3][0] = tanh2_b(acc[1][t][0], acc[1][t][1], bA);
                a3[t][3][1] = tanh2_b(acc[1][t][2], acc[1][t][3], bA);
                a3[t][3][2] = tanh2_b(acc[1][t][4], acc[1][t][5], bB);
                a3[t][3][3] = tanh2_b(acc[1][t][6], acc[1][t][7], bB);
            }
        }

        // ======== Layer 3: [32x64] @ [64x16] ========
        float acc3[2][8];
#pragma unroll
        for (int t = 0; t < 2; t++)
#pragma unroll
            for (int i = 0; i < 8; i++) acc3[t][i] = 0.f;
#pragma unroll
        for (int kk = 0; kk < 4; kk++) {
            uint32_t bh[4];
            ldsm4(bh, w3 + (uint32_t)(kk * 512));
            mma16816(&acc3[0][0], a3[0][kk], bh[0], bh[1]);
            mma16816(&acc3[0][4], a3[0][kk], bh[2], bh[3]);
            mma16816(&acc3[1][0], a3[1][kk], bh[0], bh[1]);
            mma16816(&acc3[1][4], a3[1][kk], bh[2], bh[3]);
        }

        // ======== epilogue 3 + Layer 4 dot + logits (f32 path) ========
        float2 bpA = *(float2*)&sB3[2 * q];
        float2 bpB = *(float2*)&sB3[8 + 2 * q];
        float2 wpA = *(float2*)&sW4[2 * q];
        float2 wpB = *(float2*)&sW4[8 + 2 * q];
#pragma unroll
        for (int t = 0; t < 2; t++) {
            float s0 = 0.0f, s1 = 0.0f;
            s0 = fmaf(tanh_b(acc3[t][0], bpA.x), wpA.x, s0);
            s0 = fmaf(tanh_b(acc3[t][1], bpA.y), wpA.y, s0);
            s1 = fmaf(tanh_b(acc3[t][2], bpA.x), wpA.x, s1);
            s1 = fmaf(tanh_b(acc3[t][3], bpA.y), wpA.y, s1);
            s0 = fmaf(tanh_b(acc3[t][4], bpB.x), wpB.x, s0);
            s0 = fmaf(tanh_b(acc3[t][5], bpB.y), wpB.y, s0);
            s1 = fmaf(tanh_b(acc3[t][6], bpB.x), wpB.x, s1);
            s1 = fmaf(tanh_b(acc3[t][7], bpB.y), wpB.y, s1);
            s0 += __shfl_xor_sync(0xffffffffu, s0, 1);
            s0 += __shfl_xor_sync(0xffffffffu, s0, 2);
            s1 += __shfl_xor_sync(0xffffffffu, s1, 1);
            s1 += __shfl_xor_sync(0xffffffffu, s1, 2);
            if (q == 0) {
                g_logits[base + 16 * t + g]     = s0 + bb4;
                g_logits[base + 16 * t + g + 8] = s1 + bb4;
            }
        }
    }
}

// ---------------------------------------------------------------------------
// Per-segment softmax (global-max subtraction cancels mathematically).
// ---------------------------------------------------------------------------
#define SOFT_THREADS 512

__device__ __forceinline__ float wmax(float v) {
#pragma unroll
    for (int o = 16; o > 0; o >>= 1) v = fmaxf(v, __shfl_xor_sync(0xffffffffu, v, o));
    return v;
}
__device__ __forceinline__ float wsum(float v) {
#pragma unroll
    for (int o = 16; o > 0; o >>= 1) v += __shfl_xor_sync(0xffffffffu, v, o);
    return v;
}
__device__ __forceinline__ int wsumi(int v) {
#pragma unroll
    for (int o = 16; o > 0; o >>= 1) v += __shfl_xor_sync(0xffffffffu, v, o);
    return v;
}

__global__ void __launch_bounds__(SOFT_THREADS)
softmax_seg_kernel(const int* __restrict__ sizes, float* __restrict__ out) {
    __shared__ float shf[16];
    __shared__ int shi[16];
    __shared__ float bcastf;
    __shared__ int bcasti;

    const int b = blockIdx.x, tid = threadIdx.x;
    const int wid = tid >> 5, lid = tid & 31;
    const int nwarp = SOFT_THREADS / 32;

    int part = 0;
    for (int i = tid; i < b; i += SOFT_THREADS) part += sizes[i];
    part = wsumi(part);
    if (lid == 0) shi[wid] = part;
    __syncthreads();
    if (wid == 0) {
        int v = (lid < nwarp) ? shi[lid] : 0;
        v = wsumi(v);
        if (lid == 0) bcasti = v;
    }
    __syncthreads();
    const int off = bcasti;
    const int len = sizes[b];

    float mx = -3.402823466e38f;
    for (int i = tid; i < len; i += SOFT_THREADS) mx = fmaxf(mx, g_logits[off + i]);
    mx = wmax(mx);
    if (lid == 0) shf[wid] = mx;
    __syncthreads();
    if (wid == 0) {
        float v = (lid < nwarp) ? shf[lid] : -3.402823466e38f;
        v = wmax(v);
        if (lid == 0) bcastf = v;
    }
    __syncthreads();
    mx = bcastf;

    float s = 0.0f;
    for (int i = tid; i < len; i += SOFT_THREADS) {
        float e = __expf(g_logits[off + i] - mx);
        out[off + i] = e;
        s += e;
    }
    s = wsum(s);
    __syncthreads();
    if (lid == 0) shf[wid] = s;
    __syncthreads();
    if (wid == 0) {
        float v = (lid < nwarp) ? shf[lid] : 0.0f;
        v = wsum(v);
        if (lid == 0) bcastf = v;
    }
    __syncthreads();
    const float inv = 1.0f / bcastf;

    for (int i = tid; i < len; i += SOFT_THREADS) out[off + i] *= inv;
}

__global__ void tail_sizes_kernel(const int* __restrict__ sizes, float* __restrict__ out,
                                  int n, int basepos) {
    int i = blockIdx.x * blockDim.x + threadIdx.x;
    if (i < n) out[basepos + i] = (float)sizes[i];
}

// ---------------------------------------------------------------------------
extern "C" void kernel_launch(void* const* d_in, const int* in_sizes, int n_in,
                              void* d_out, int out_size) {
    const float* x   = (const float*)d_in[0];
    const int* sizes = (const int*)d_in[1];
    const float* W1  = (const float*)d_in[2];
    const float* b1  = (const float*)d_in[3];
    const float* W2  = (const float*)d_in[4];
    const float* b2  = (const float*)d_in[5];
    const float* W3  = (const float*)d_in[6];
    const float* b3  = (const float*)d_in[7];
    const float* W4  = (const float*)d_in[8];
    const float* b4  = (const float*)d_in[9];
    float* out = (float*)d_out;

    const int total  = in_sizes[0] / D_IN;
    const int B      = in_sizes[1];
    const int nunits = total / 32;

    cudaFuncSetAttribute(mlp_hmma_kernel, cudaFuncAttributeMaxDynamicSharedMemorySize, SMEM_BYTES);

    mlp_hmma_kernel<<<PERSIST_BLOCKS, THREADS, SMEM_BYTES>>>(x, nunits, W1, b1, W2, b2, W3, b3, W4, b4);
    softmax_seg_kernel<<<B, SOFT_THREADS>>>(sizes, out);

    if (out_size > total) {
        int n = out_size - total;
        tail_sizes_kernel<<<(n + 255) / 256, 256>>>(sizes, out, n, total);
    }
}

// round 13
// speedup vs baseline: 1.6408x; 1.6408x over previous
#include <cuda_runtime.h>
#include <cuda_fp16.h>
#include <stdint.h>

#define THREADS 384          // 12 warps -> 3 per SMSP
#define D_IN 64
#define PERSIST_BLOCKS 148   // 1 CTA per SM

// ---- smem byte offsets: LDSM-tiled weights (8n x 8k fp16 tiles, 16B rows) ----
#define W1_B  0          // 32 blocks x 512B = 16384
#define W2_B  16384      // 32 blocks x 512B = 16384
#define W3_B  32768      // 4 blocks x 512B = 2048
#define B1_B  34816      // half2-packed biases: 64 x u32
#define B2_B  35072      // 32 x u32
#define B3_B  35200      // f32[16]
#define W4_B  35264      // f32[16]
#define SMEM_BYTES 35328

__device__ float g_logits[1 << 20];

// ---- helpers ----
__device__ __forceinline__ uint32_t smem_u32(const void* p) {
    uint32_t a;
    asm("{ .reg .u64 t; cvta.to.shared.u64 t, %1; cvt.u32.u64 %0, t; }" : "=r"(a) : "l"(p));
    return a;
}
// f32-accumulate HMMA (layer 3 only)
__device__ __forceinline__ void mma16816(float* c, const uint32_t* a, uint32_t b0, uint32_t b1) {
    asm volatile(
        "mma.sync.aligned.m16n8k16.row.col.f32.f16.f16.f32 "
        "{%0,%1,%2,%3}, {%4,%5,%6,%7}, {%8,%9}, {%0,%1,%2,%3};"
        : "+f"(c[0]), "+f"(c[1]), "+f"(c[2]), "+f"(c[3])
        : "r"(a[0]), "r"(a[1]), "r"(a[2]), "r"(a[3]), "r"(b0), "r"(b1));
}
// f16-accumulate HMMA (layers 1 & 2): D/C packed f16x2, 2 regs
// c[0] = (row g,   col 2q | 2q+1), c[1] = (row g+8, col 2q | 2q+1)
__device__ __forceinline__ void mma16816h(uint32_t* c, const uint32_t* a, uint32_t b0, uint32_t b1) {
    asm volatile(
        "mma.sync.aligned.m16n8k16.row.col.f16.f16.f16.f16 "
        "{%0,%1}, {%2,%3,%4,%5}, {%6,%7}, {%0,%1};"
        : "+r"(c[0]), "+r"(c[1])
        : "r"(a[0]), "r"(a[1]), "r"(a[2]), "r"(a[3]), "r"(b0), "r"(b1));
}
__device__ __forceinline__ void ldsm4(uint32_t* d, uint32_t addr) {
    asm volatile("ldmatrix.sync.aligned.m8n8.x4.shared.b16 {%0,%1,%2,%3}, [%4];"
        : "=r"(d[0]), "=r"(d[1]), "=r"(d[2]), "=r"(d[3]) : "r"(addr));
}
__device__ __forceinline__ void prefetchL2(const void* p) {
    asm volatile("prefetch.global.L2 [%0];" :: "l"(p));
}
__device__ __forceinline__ uint32_t packh2(float a, float b) {
    __half2 h = __floats2half2_rn(a, b);
    return *(uint32_t*)&h;
}
// tanh of packed f16x2 word (bias pre-seeded in the accumulator)
__device__ __forceinline__ uint32_t tanh2(uint32_t v) {
    uint32_t r;
    asm("tanh.approx.f16x2 %0, %1;" : "=r"(r) : "r"(v));
    return r;
}
__device__ __forceinline__ float tanh_b(float acc, float b) {
    float s = acc + b;
    float r; asm("tanh.approx.f32 %0, %1;" : "=f"(r) : "f"(s));
    return r;
}

// ---------------------------------------------------------------------------
// Persistent fused MLP, 32 tokens per warp per unit, zero loop barriers.
// r13: layers 1&2 use f16-ACCUMULATE HMMA (2x rate if f32-accum is half-rate
// on this unit), bias pre-seeded into the f16 accumulator, epilogue = one
// tanh.approx.f16x2 per output word (no cvt/add at all).
// ---------------------------------------------------------------------------
__global__ void __launch_bounds__(THREADS, 1)
mlp_hmma_kernel(const float* __restrict__ x, int nunits,
                const float* __restrict__ W1, const float* __restrict__ b1,
                const float* __restrict__ W2, const float* __restrict__ b2,
                const float* __restrict__ W3, const float* __restrict__ b3,
                const float* __restrict__ W4, const float* __restrict__ b4) {
    extern __shared__ char smem[];
    uint32_t* sB1 = (uint32_t*)(smem + B1_B);   // half2-packed
    uint32_t* sB2 = (uint32_t*)(smem + B2_B);   // half2-packed
    float* sB3 = (float*)(smem + B3_B);
    float* sW4 = (float*)(smem + W4_B);

    const int tid = threadIdx.x;

    // ---- stage weights once into LDSM tile layout (single fp16) ----
    for (int i = tid; i < 8192; i += THREADS) {   // W1: [64k x 128n]
        int k = i >> 7, n = i & 127;
        __half h = __float2half_rn(W1[i]);
        int kk = k >> 4, khalf = (k >> 3) & 1, kin = k & 7;
        int jp = n >> 4, j01 = (n >> 3) & 1, nin = n & 7;
        uint32_t off = ((((jp << 2) + kk) * 4 + j01 * 2 + khalf) << 7) + (nin << 4) + (kin << 1);
        *(__half*)(smem + W1_B + off) = h;
    }
    for (int i = tid; i < 8192; i += THREADS) {   // W2: [128k x 64n]
        int k = i >> 6, n = i & 63;
        __half h = __float2half_rn(W2[i]);
        int kk = k >> 4, khalf = (k >> 3) & 1, kin = k & 7;
        int jp = n >> 4, j01 = (n >> 3) & 1, nin = n & 7;
        uint32_t off = ((((jp << 3) + kk) * 4 + j01 * 2 + khalf) << 7) + (nin << 4) + (kin << 1);
        *(__half*)(smem + W2_B + off) = h;
    }
    for (int i = tid; i < 1024; i += THREADS) {   // W3: [64k x 16n]
        int k = i >> 4, n = i & 15;
        __half h = __float2half_rn(W3[i]);
        int kk = k >> 4, khalf = (k >> 3) & 1, kin = k & 7;
        int j01 = (n >> 3) & 1, nin = n & 7;
        uint32_t off = (((kk << 2) + j01 * 2 + khalf) << 7) + (nin << 4) + (kin << 1);
        *(__half*)(smem + W3_B + off) = h;
    }
    if (tid < 64) sB1[tid] = packh2(b1[2 * tid], b1[2 * tid + 1]);
    else if (tid >= 64 && tid < 96) sB2[tid - 64] = packh2(b2[2 * (tid - 64)], b2[2 * (tid - 64) + 1]);
    else if (tid >= 96 && tid < 112) { sB3[tid - 96] = b3[tid - 96]; sW4[tid - 96] = W4[tid - 96]; }
    __syncthreads();

    const int wid = tid >> 5, lid = tid & 31;
    const int g  = lid >> 2;        // group row 0..7
    const int q  = lid & 3;         // quad col 0..3
    const float bb4 = b4[0];

    const uint32_t smb = smem_u32(smem);
    const uint32_t lane16 = (uint32_t)lid << 4;
    const uint32_t w1 = smb + W1_B + lane16;
    const uint32_t w2 = smb + W2_B + lane16;
    const uint32_t w3 = smb + W3_B + lane16;

    const int nwarps = gridDim.x * (THREADS / 32);
    // -------- persistent unit loop: 32 tokens per warp per iteration --------
    for (int u = blockIdx.x * (THREADS / 32) + wid; u < nunits; u += nwarps) {
        const long long base = (long long)u << 5;
        const float* xw = x + base * D_IN;

        // ---- A1 fragments straight from gmem (fp16), 2 m16 tiles ----
        uint32_t a1[2][4][4];
#pragma unroll
        for (int t = 0; t < 2; t++) {
            const float* xt = xw + t * 16 * D_IN;
#pragma unroll
            for (int kk = 0; kk < 4; kk++) {
                int c0 = q * 2 + 16 * kk;
                float2 p00 = *(const float2*)&xt[g * D_IN + c0];
                float2 p10 = *(const float2*)&xt[(g + 8) * D_IN + c0];
                float2 p01 = *(const float2*)&xt[g * D_IN + c0 + 8];
                float2 p11 = *(const float2*)&xt[(g + 8) * D_IN + c0 + 8];
                a1[t][kk][0] = packh2(p00.x, p00.y);
                a1[t][kk][1] = packh2(p10.x, p10.y);
                a1[t][kk][2] = packh2(p01.x, p01.y);
                a1[t][kk][3] = packh2(p11.x, p11.y);
            }
        }

        // ---- prefetch next unit's X rows into L2 ----
        {
            int nu = u + nwarps;
            if (nu < nunits) {
                const float* nx = x + ((long long)nu << 5) * D_IN;
                prefetchL2(&nx[g * D_IN + q * 16]);
                prefetchL2(&nx[(g + 8) * D_IN + q * 16]);
                prefetchL2(&nx[(g + 16) * D_IN + q * 16]);
                prefetchL2(&nx[(g + 24) * D_IN + q * 16]);
            }
        }

        // ======== Layer 1: [32x64] @ [64x128], f16-accum, bias-seeded ======
        uint32_t a2[2][8][4];
#pragma unroll
        for (int jp = 0; jp < 8; jp++) {
            const uint32_t bA = sB1[8 * jp + q];
            const uint32_t bB = sB1[8 * jp + 4 + q];
            uint32_t accP[2][2], accQ[2][2];
#pragma unroll
            for (int t = 0; t < 2; t++) {
                accP[t][0] = bA; accP[t][1] = bA;
                accQ[t][0] = bB; accQ[t][1] = bB;
            }
#pragma unroll
            for (int kk = 0; kk < 4; kk++) {
                uint32_t bh[4];
                ldsm4(bh, w1 + (uint32_t)(jp * 2048 + kk * 512));
                mma16816h(accP[0], a1[0][kk], bh[0], bh[1]);
                mma16816h(accQ[0], a1[0][kk], bh[2], bh[3]);
                mma16816h(accP[1], a1[1][kk], bh[0], bh[1]);
                mma16816h(accQ[1], a1[1][kk], bh[2], bh[3]);
            }
#pragma unroll
            for (int t = 0; t < 2; t++) {
                a2[t][jp][0] = tanh2(accP[t][0]);
                a2[t][jp][1] = tanh2(accP[t][1]);
                a2[t][jp][2] = tanh2(accQ[t][0]);
                a2[t][jp][3] = tanh2(accQ[t][1]);
            }
        }

        // ======== Layer 2: [32x128] @ [128x64], f16-accum, bias-seeded =====
        uint32_t a3[2][4][4];
#pragma unroll
        for (int jp = 0; jp < 4; jp++) {
            const uint32_t bA = sB2[8 * jp + q];
            const uint32_t bB = sB2[8 * jp + 4 + q];
            uint32_t accP[2][2], accQ[2][2];
#pragma unroll
            for (int t = 0; t < 2; t++) {
                accP[t][0] = bA; accP[t][1] = bA;
                accQ[t][0] = bB; accQ[t][1] = bB;
            }
#pragma unroll
            for (int kk = 0; kk < 8; kk++) {
                uint32_t bh[4];
                ldsm4(bh, w2 + (uint32_t)(jp * 4096 + kk * 512));
                mma16816h(accP[0], a2[0][kk], bh[0], bh[1]);
                mma16816h(accQ[0], a2[0][kk], bh[2], bh[3]);
                mma16816h(accP[1], a2[1][kk], bh[0], bh[1]);
                mma16816h(accQ[1], a2[1][kk], bh[2], bh[3]);
            }
#pragma unroll
            for (int t = 0; t < 2; t++) {
                a3[t][jp][0] = tanh2(accP[t][0]);
                a3[t][jp][1] = tanh2(accP[t][1]);
                a3[t][jp][2] = tanh2(accQ[t][0]);
                a3[t][jp][3] = tanh2(accQ[t][1]);
            }
        }

        // ======== Layer 3: [32x64] @ [64x16], f32 accum ========
        float acc3[2][8];
#pragma unroll
        for (int t = 0; t < 2; t++)
#pragma unroll
            for (int i = 0; i < 8; i++) acc3[t][i] = 0.f;
#pragma unroll
        for (int kk = 0; kk < 4; kk++) {
            uint32_t bh[4];
            ldsm4(bh, w3 + (uint32_t)(kk * 512));
            mma16816(&acc3[0][0], a3[0][kk], bh[0], bh[1]);
            mma16816(&acc3[0][4], a3[0][kk], bh[2], bh[3]);
            mma16816(&acc3[1][0], a3[1][kk], bh[0], bh[1]);
            mma16816(&acc3[1][4], a3[1][kk], bh[2], bh[3]);
        }

        // ======== epilogue 3 + Layer 4 dot + logits (f32 path) ========
        float2 bpA = *(float2*)&sB3[2 * q];
        float2 bpB = *(float2*)&sB3[8 + 2 * q];
        float2 wpA = *(float2*)&sW4[2 * q];
        float2 wpB = *(float2*)&sW4[8 + 2 * q];
#pragma unroll
        for (int t = 0; t < 2; t++) {
            float s0 = 0.0f, s1 = 0.0f;
            s0 = fmaf(tanh_b(acc3[t][0], bpA.x), wpA.x, s0);
            s0 = fmaf(tanh_b(acc3[t][1], bpA.y), wpA.y, s0);
            s1 = fmaf(tanh_b(acc3[t][2], bpA.x), wpA.x, s1);
            s1 = fmaf(tanh_b(acc3[t][3], bpA.y), wpA.y, s1);
            s0 = fmaf(tanh_b(acc3[t][4], bpB.x), wpB.x, s0);
            s0 = fmaf(tanh_b(acc3[t][5], bpB.y), wpB.y, s0);
            s1 = fmaf(tanh_b(acc3[t][6], bpB.x), wpB.x, s1);
            s1 = fmaf(tanh_b(acc3[t][7], bpB.y), wpB.y, s1);
            s0 += __shfl_xor_sync(0xffffffffu, s0, 1);
            s0 += __shfl_xor_sync(0xffffffffu, s0, 2);
            s1 += __shfl_xor_sync(0xffffffffu, s1, 1);
            s1 += __shfl_xor_sync(0xffffffffu, s1, 2);
            if (q == 0) {
                g_logits[base + 16 * t + g]     = s0 + bb4;
                g_logits[base + 16 * t + g + 8] = s1 + bb4;
            }
        }
    }
}

// ---------------------------------------------------------------------------
// Per-segment softmax (global-max subtraction cancels mathematically).
// ---------------------------------------------------------------------------
#define SOFT_THREADS 512

__device__ __forceinline__ float wmax(float v) {
#pragma unroll
    for (int o = 16; o > 0; o >>= 1) v = fmaxf(v, __shfl_xor_sync(0xffffffffu, v, o));
    return v;
}
__device__ __forceinline__ float wsum(float v) {
#pragma unroll
    for (int o = 16; o > 0; o >>= 1) v += __shfl_xor_sync(0xffffffffu, v, o);
    return v;
}
__device__ __forceinline__ int wsumi(int v) {
#pragma unroll
    for (int o = 16; o > 0; o >>= 1) v += __shfl_xor_sync(0xffffffffu, v, o);
    return v;
}

__global__ void __launch_bounds__(SOFT_THREADS)
softmax_seg_kernel(const int* __restrict__ sizes, float* __restrict__ out) {
    __shared__ float shf[16];
    __shared__ int shi[16];
    __shared__ float bcastf;
    __shared__ int bcasti;

    const int b = blockIdx.x, tid = threadIdx.x;
    const int wid = tid >> 5, lid = tid & 31;
    const int nwarp = SOFT_THREADS / 32;

    int part = 0;
    for (int i = tid; i < b; i += SOFT_THREADS) part += sizes[i];
    part = wsumi(part);
    if (lid == 0) shi[wid] = part;
    __syncthreads();
    if (wid == 0) {
        int v = (lid < nwarp) ? shi[lid] : 0;
        v = wsumi(v);
        if (lid == 0) bcasti = v;
    }
    __syncthreads();
    const int off = bcasti;
    const int len = sizes[b];

    float mx = -3.402823466e38f;
    for (int i = tid; i < len; i += SOFT_THREADS) mx = fmaxf(mx, g_logits[off + i]);
    mx = wmax(mx);
    if (lid == 0) shf[wid] = mx;
    __syncthreads();
    if (wid == 0) {
        float v = (lid < nwarp) ? shf[lid] : -3.402823466e38f;
        v = wmax(v);
        if (lid == 0) bcastf = v;
    }
    __syncthreads();
    mx = bcastf;

    float s = 0.0f;
    for (int i = tid; i < len; i += SOFT_THREADS) {
        float e = __expf(g_logits[off + i] - mx);
        out[off + i] = e;
        s += e;
    }
    s = wsum(s);
    __syncthreads();
    if (lid == 0) shf[wid] = s;
    __syncthreads();
    if (wid == 0) {
        float v = (lid < nwarp) ? shf[lid] : 0.0f;
        v = wsum(v);
        if (lid == 0) bcastf = v;
    }
    __syncthreads();
    const float inv = 1.0f / bcastf;

    for (int i = tid; i < len; i += SOFT_THREADS) out[off + i] *= inv;
}

__global__ void tail_sizes_kernel(const int* __restrict__ sizes, float* __restrict__ out,
                                  int n, int basepos) {
    int i = blockIdx.x * blockDim.x + threadIdx.x;
    if (i < n) out[basepos + i] = (float)sizes[i];
}

// ---------------------------------------------------------------------------
extern "C" void kernel_launch(void* const* d_in, const int* in_sizes, int n_in,
                              void* d_out, int out_size) {
    const float* x   = (const float*)d_in[0];
    const int* sizes = (const int*)d_in[1];
    const float* W1  = (const float*)d_in[2];
    const float* b1  = (const float*)d_in[3];
    const float* W2  = (const float*)d_in[4];
    const float* b2  = (const float*)d_in[5];
    const float* W3  = (const float*)d_in[6];
    const float* b3  = (const float*)d_in[7];
    const float* W4  = (const float*)d_in[8];
    const float* b4  = (const float*)d_in[9];
    float* out = (float*)d_out;

    const int total  = in_sizes[0] / D_IN;
    const int B      = in_sizes[1];
    const int nunits = total / 32;

    cudaFuncSetAttribute(mlp_hmma_kernel, cudaFuncAttributeMaxDynamicSharedMemorySize, SMEM_BYTES);

    mlp_hmma_kernel<<<PERSIST_BLOCKS, THREADS, SMEM_BYTES>>>(x, nunits, W1, b1, W2, b2, W3, b3, W4, b4);
    softmax_seg_kernel<<<B, SOFT_THREADS>>>(sizes, out);

    if (out_size > total) {
        int n = out_size - total;
        tail_sizes_kernel<<<(n + 255) / 256, 256>>>(sizes, out, n, total);
    }
}

// round 14
// speedup vs baseline: 1.8194x; 1.1089x over previous
#include <cuda_runtime.h>
#include <cuda_fp16.h>
#include <stdint.h>

#define THREADS 384          // 12 warps -> 3 per SMSP
#define D_IN 64
#define PERSIST_BLOCKS 148   // 1 CTA per SM

// ---- smem byte offsets: LDSM-tiled weights (8n x 8k fp16 tiles, 16B rows) ----
#define W1_B  0          // 32 blocks x 512B = 16384
#define W2_B  16384      // 32 blocks x 512B = 16384
#define W3_B  32768      // 4 blocks x 512B = 2048
#define B1_B  34816      // half2-packed biases: 64 x u32
#define B2_B  35072      // 32 x u32
#define B3_B  35200      // f32[16]
#define W4_B  35264      // f32[16]
#define SMEM_BYTES 35328

__device__ float g_logits[1 << 20];

// ---- helpers ----
__device__ __forceinline__ uint32_t smem_u32(const void* p) {
    uint32_t a;
    asm("{ .reg .u64 t; cvta.to.shared.u64 t, %1; cvt.u32.u64 %0, t; }" : "=r"(a) : "l"(p));
    return a;
}
// f32-accumulate HMMA (layer 3 only)
__device__ __forceinline__ void mma16816(float* c, const uint32_t* a, uint32_t b0, uint32_t b1) {
    asm volatile(
        "mma.sync.aligned.m16n8k16.row.col.f32.f16.f16.f32 "
        "{%0,%1,%2,%3}, {%4,%5,%6,%7}, {%8,%9}, {%0,%1,%2,%3};"
        : "+f"(c[0]), "+f"(c[1]), "+f"(c[2]), "+f"(c[3])
        : "r"(a[0]), "r"(a[1]), "r"(a[2]), "r"(a[3]), "r"(b0), "r"(b1));
}
// f16-accumulate HMMA (layers 1 & 2): D/C packed f16x2, 2 regs
__device__ __forceinline__ void mma16816h(uint32_t* c, const uint32_t* a, uint32_t b0, uint32_t b1) {
    asm volatile(
        "mma.sync.aligned.m16n8k16.row.col.f16.f16.f16.f16 "
        "{%0,%1}, {%2,%3,%4,%5}, {%6,%7}, {%0,%1};"
        : "+r"(c[0]), "+r"(c[1])
        : "r"(a[0]), "r"(a[1]), "r"(a[2]), "r"(a[3]), "r"(b0), "r"(b1));
}
__device__ __forceinline__ void ldsm4(uint32_t* d, uint32_t addr) {
    asm volatile("ldmatrix.sync.aligned.m8n8.x4.shared.b16 {%0,%1,%2,%3}, [%4];"
        : "=r"(d[0]), "=r"(d[1]), "=r"(d[2]), "=r"(d[3]) : "r"(addr));
}
__device__ __forceinline__ void prefetchL2(const void* p) {
    asm volatile("prefetch.global.L2 [%0];" :: "l"(p));
}
__device__ __forceinline__ uint32_t packh2(float a, float b) {
    __half2 h = __floats2half2_rn(a, b);
    return *(uint32_t*)&h;
}
__device__ __forceinline__ uint32_t tanh2(uint32_t v) {
    uint32_t r;
    asm("tanh.approx.f16x2 %0, %1;" : "=r"(r) : "r"(v));
    return r;
}
__device__ __forceinline__ float tanh_b(float acc, float b) {
    float s = acc + b;
    float r; asm("tanh.approx.f32 %0, %1;" : "=f"(r) : "f"(s));
    return r;
}

// load 32-token X block into A1 fragments (fp16), 2 m16 tiles
__device__ __forceinline__ void load_a1(const float* __restrict__ xw,
                                        int g, int q, uint32_t a1[2][4][4]) {
#pragma unroll
    for (int t = 0; t < 2; t++) {
        const float* xt = xw + t * 16 * D_IN;
#pragma unroll
        for (int kk = 0; kk < 4; kk++) {
            int c0 = q * 2 + 16 * kk;
            float2 p00 = *(const float2*)&xt[g * D_IN + c0];
            float2 p10 = *(const float2*)&xt[(g + 8) * D_IN + c0];
            float2 p01 = *(const float2*)&xt[g * D_IN + c0 + 8];
            float2 p11 = *(const float2*)&xt[(g + 8) * D_IN + c0 + 8];
            a1[t][kk][0] = packh2(p00.x, p00.y);
            a1[t][kk][1] = packh2(p10.x, p10.y);
            a1[t][kk][2] = packh2(p01.x, p01.y);
            a1[t][kk][3] = packh2(p11.x, p11.y);
        }
    }
}

// ---------------------------------------------------------------------------
// Persistent fused MLP, 32 tokens per warp per unit, zero loop barriers.
// r14: kk-outer dataflow fusion of layers 1&2 — L2's k-step kk consumes L1's
// output group jp=kk immediately, so tanh2 (MUFU) and L2 MMAs overlap L1 MMAs
// of the next kk. Next unit's X loaded into registers under the L3 tail.
// ---------------------------------------------------------------------------
__global__ void __launch_bounds__(THREADS, 1)
mlp_hmma_kernel(const float* __restrict__ x, int nunits,
                const float* __restrict__ W1, const float* __restrict__ b1,
                const float* __restrict__ W2, const float* __restrict__ b2,
                const float* __restrict__ W3, const float* __restrict__ b3,
                const float* __restrict__ W4, const float* __restrict__ b4) {
    extern __shared__ char smem[];
    uint32_t* sB1 = (uint32_t*)(smem + B1_B);   // half2-packed
    uint32_t* sB2 = (uint32_t*)(smem + B2_B);   // half2-packed
    float* sB3 = (float*)(smem + B3_B);
    float* sW4 = (float*)(smem + W4_B);

    const int tid = threadIdx.x;

    // ---- stage weights once into LDSM tile layout (single fp16) ----
    for (int i = tid; i < 8192; i += THREADS) {   // W1: [64k x 128n]
        int k = i >> 7, n = i & 127;
        __half h = __float2half_rn(W1[i]);
        int kk = k >> 4, khalf = (k >> 3) & 1, kin = k & 7;
        int jp = n >> 4, j01 = (n >> 3) & 1, nin = n & 7;
        uint32_t off = ((((jp << 2) + kk) * 4 + j01 * 2 + khalf) << 7) + (nin << 4) + (kin << 1);
        *(__half*)(smem + W1_B + off) = h;
    }
    for (int i = tid; i < 8192; i += THREADS) {   // W2: [128k x 64n]
        int k = i >> 6, n = i & 63;
        __half h = __float2half_rn(W2[i]);
        int kk = k >> 4, khalf = (k >> 3) & 1, kin = k & 7;
        int jp = n >> 4, j01 = (n >> 3) & 1, nin = n & 7;
        uint32_t off = ((((jp << 3) + kk) * 4 + j01 * 2 + khalf) << 7) + (nin << 4) + (kin << 1);
        *(__half*)(smem + W2_B + off) = h;
    }
    for (int i = tid; i < 1024; i += THREADS) {   // W3: [64k x 16n]
        int k = i >> 4, n = i & 15;
        __half h = __float2half_rn(W3[i]);
        int kk = k >> 4, khalf = (k >> 3) & 1, kin = k & 7;
        int j01 = (n >> 3) & 1, nin = n & 7;
        uint32_t off = (((kk << 2) + j01 * 2 + khalf) << 7) + (nin << 4) + (kin << 1);
        *(__half*)(smem + W3_B + off) = h;
    }
    if (tid < 64) sB1[tid] = packh2(b1[2 * tid], b1[2 * tid + 1]);
    else if (tid >= 64 && tid < 96) sB2[tid - 64] = packh2(b2[2 * (tid - 64)], b2[2 * (tid - 64) + 1]);
    else if (tid >= 96 && tid < 112) { sB3[tid - 96] = b3[tid - 96]; sW4[tid - 96] = W4[tid - 96]; }
    __syncthreads();

    const int wid = tid >> 5, lid = tid & 31;
    const int g  = lid >> 2;        // group row 0..7
    const int q  = lid & 3;         // quad col 0..3
    const float bb4 = b4[0];

    const uint32_t smb = smem_u32(smem);
    const uint32_t lane16 = (uint32_t)lid << 4;
    const uint32_t w1 = smb + W1_B + lane16;
    const uint32_t w2 = smb + W2_B + lane16;
    const uint32_t w3 = smb + W3_B + lane16;

    const int nwarps = gridDim.x * (THREADS / 32);
    const int u0 = blockIdx.x * (THREADS / 32) + wid;

    uint32_t a1[2][4][4];
    if (u0 < nunits) load_a1(x + ((long long)u0 << 5) * D_IN, g, q, a1);

    // -------- persistent unit loop: 32 tokens per warp per iteration --------
    for (int u = u0; u < nunits; u += nwarps) {
        const long long base = (long long)u << 5;

        // ---- prefetch next unit's X rows into L2 cache ----
        const int nu = u + nwarps;
        if (nu < nunits) {
            const float* nx = x + ((long long)nu << 5) * D_IN;
            prefetchL2(&nx[g * D_IN + q * 16]);
            prefetchL2(&nx[(g + 8) * D_IN + q * 16]);
            prefetchL2(&nx[(g + 16) * D_IN + q * 16]);
            prefetchL2(&nx[(g + 24) * D_IN + q * 16]);
        }

        // ======== Fused layers 1+2, kk-outer ========
        // L2 accumulators (f16x2, bias-seeded): [jp2][t][2] for n-lo(P)/n-hi(Q)
        uint32_t acc2P[4][2][2], acc2Q[4][2][2];
#pragma unroll
        for (int jp2 = 0; jp2 < 4; jp2++) {
            const uint32_t bA = sB2[8 * jp2 + q];
            const uint32_t bB = sB2[8 * jp2 + 4 + q];
#pragma unroll
            for (int t = 0; t < 2; t++) {
                acc2P[jp2][t][0] = bA; acc2P[jp2][t][1] = bA;
                acc2Q[jp2][t][0] = bB; acc2Q[jp2][t][1] = bB;
            }
        }
#pragma unroll
        for (int kk = 0; kk < 8; kk++) {
            // ---- L1 output group jp = kk ----
            const uint32_t bA = sB1[8 * kk + q];
            const uint32_t bB = sB1[8 * kk + 4 + q];
            uint32_t aP[2][2], aQ[2][2];
#pragma unroll
            for (int t = 0; t < 2; t++) {
                aP[t][0] = bA; aP[t][1] = bA;
                aQ[t][0] = bB; aQ[t][1] = bB;
            }
#pragma unroll
            for (int k1 = 0; k1 < 4; k1++) {
                uint32_t bh[4];
                ldsm4(bh, w1 + (uint32_t)(kk * 2048 + k1 * 512));
                mma16816h(aP[0], a1[0][k1], bh[0], bh[1]);
                mma16816h(aQ[0], a1[0][k1], bh[2], bh[3]);
                mma16816h(aP[1], a1[1][k1], bh[0], bh[1]);
                mma16816h(aQ[1], a1[1][k1], bh[2], bh[3]);
            }
            uint32_t a2k[2][4];
#pragma unroll
            for (int t = 0; t < 2; t++) {
                a2k[t][0] = tanh2(aP[t][0]);
                a2k[t][1] = tanh2(aP[t][1]);
                a2k[t][2] = tanh2(aQ[t][0]);
                a2k[t][3] = tanh2(aQ[t][1]);
            }
            // ---- L2 k-step kk into persistent accumulators ----
#pragma unroll
            for (int jp2 = 0; jp2 < 4; jp2++) {
                uint32_t bh[4];
                ldsm4(bh, w2 + (uint32_t)(jp2 * 4096 + kk * 512));
                mma16816h(acc2P[jp2][0], a2k[0], bh[0], bh[1]);
                mma16816h(acc2Q[jp2][0], a2k[0], bh[2], bh[3]);
                mma16816h(acc2P[jp2][1], a2k[1], bh[0], bh[1]);
                mma16816h(acc2Q[jp2][1], a2k[1], bh[2], bh[3]);
            }
        }

        // ---- load NEXT unit's X into a1 now (a1 dead; hides LDG under tail)
        if (nu < nunits) load_a1(x + ((long long)nu << 5) * D_IN, g, q, a1);

        // ---- L2 epilogue -> a3 fragments ----
        uint32_t a3[2][4][4];
#pragma unroll
        for (int jp2 = 0; jp2 < 4; jp2++)
#pragma unroll
            for (int t = 0; t < 2; t++) {
                a3[t][jp2][0] = tanh2(acc2P[jp2][t][0]);
                a3[t][jp2][1] = tanh2(acc2P[jp2][t][1]);
                a3[t][jp2][2] = tanh2(acc2Q[jp2][t][0]);
                a3[t][jp2][3] = tanh2(acc2Q[jp2][t][1]);
            }

        // ======== Layer 3: [32x64] @ [64x16], f32 accum ========
        float acc3[2][8];
#pragma unroll
        for (int t = 0; t < 2; t++)
#pragma unroll
            for (int i = 0; i < 8; i++) acc3[t][i] = 0.f;
#pragma unroll
        for (int kk = 0; kk < 4; kk++) {
            uint32_t bh[4];
            ldsm4(bh, w3 + (uint32_t)(kk * 512));
            mma16816(&acc3[0][0], a3[0][kk], bh[0], bh[1]);
            mma16816(&acc3[0][4], a3[0][kk], bh[2], bh[3]);
            mma16816(&acc3[1][0], a3[1][kk], bh[0], bh[1]);
            mma16816(&acc3[1][4], a3[1][kk], bh[2], bh[3]);
        }

        // ======== epilogue 3 + Layer 4 dot + logits (f32 path) ========
        float2 bpA = *(float2*)&sB3[2 * q];
        float2 bpB = *(float2*)&sB3[8 + 2 * q];
        float2 wpA = *(float2*)&sW4[2 * q];
        float2 wpB = *(float2*)&sW4[8 + 2 * q];
#pragma unroll
        for (int t = 0; t < 2; t++) {
            float s0 = 0.0f, s1 = 0.0f;
            s0 = fmaf(tanh_b(acc3[t][0], bpA.x), wpA.x, s0);
            s0 = fmaf(tanh_b(acc3[t][1], bpA.y), wpA.y, s0);
            s1 = fmaf(tanh_b(acc3[t][2], bpA.x), wpA.x, s1);
            s1 = fmaf(tanh_b(acc3[t][3], bpA.y), wpA.y, s1);
            s0 = fmaf(tanh_b(acc3[t][4], bpB.x), wpB.x, s0);
            s0 = fmaf(tanh_b(acc3[t][5], bpB.y), wpB.y, s0);
            s1 = fmaf(tanh_b(acc3[t][6], bpB.x), wpB.x, s1);
            s1 = fmaf(tanh_b(acc3[t][7], bpB.y), wpB.y, s1);
            s0 += __shfl_xor_sync(0xffffffffu, s0, 1);
            s0 += __shfl_xor_sync(0xffffffffu, s0, 2);
            s1 += __shfl_xor_sync(0xffffffffu, s1, 1);
            s1 += __shfl_xor_sync(0xffffffffu, s1, 2);
            if (q == 0) {
                g_logits[base + 16 * t + g]     = s0 + bb4;
                g_logits[base + 16 * t + g + 8] = s1 + bb4;
            }
        }
    }
}

// ---------------------------------------------------------------------------
// Per-segment softmax (global-max subtraction cancels mathematically).
// ---------------------------------------------------------------------------
#define SOFT_THREADS 512

__device__ __forceinline__ float wmax(float v) {
#pragma unroll
    for (int o = 16; o > 0; o >>= 1) v = fmaxf(v, __shfl_xor_sync(0xffffffffu, v, o));
    return v;
}
__device__ __forceinline__ float wsum(float v) {
#pragma unroll
    for (int o = 16; o > 0; o >>= 1) v += __shfl_xor_sync(0xffffffffu, v, o);
    return v;
}
__device__ __forceinline__ int wsumi(int v) {
#pragma unroll
    for (int o = 16; o > 0; o >>= 1) v += __shfl_xor_sync(0xffffffffu, v, o);
    return v;
}

__global__ void __launch_bounds__(SOFT_THREADS)
softmax_seg_kernel(const int* __restrict__ sizes, float* __restrict__ out) {
    __shared__ float shf[16];
    __shared__ int shi[16];
    __shared__ float bcastf;
    __shared__ int bcasti;

    const int b = blockIdx.x, tid = threadIdx.x;
    const int wid = tid >> 5, lid = tid & 31;
    const int nwarp = SOFT_THREADS / 32;

    int part = 0;
    for (int i = tid; i < b; i += SOFT_THREADS) part += sizes[i];
    part = wsumi(part);
    if (lid == 0) shi[wid] = part;
    __syncthreads();
    if (wid == 0) {
        int v = (lid < nwarp) ? shi[lid] : 0;
        v = wsumi(v);
        if (lid == 0) bcasti = v;
    }
    __syncthreads();
    const int off = bcasti;
    const int len = sizes[b];

    float mx = -3.402823466e38f;
    for (int i = tid; i < len; i += SOFT_THREADS) mx = fmaxf(mx, g_logits[off + i]);
    mx = wmax(mx);
    if (lid == 0) shf[wid] = mx;
    __syncthreads();
    if (wid == 0) {
        float v = (lid < nwarp) ? shf[lid] : -3.402823466e38f;
        v = wmax(v);
        if (lid == 0) bcastf = v;
    }
    __syncthreads();
    mx = bcastf;

    float s = 0.0f;
    for (int i = tid; i < len; i += SOFT_THREADS) {
        float e = __expf(g_logits[off + i] - mx);
        out[off + i] = e;
        s += e;
    }
    s = wsum(s);
    __syncthreads();
    if (lid == 0) shf[wid] = s;
    __syncthreads();
    if (wid == 0) {
        float v = (lid < nwarp) ? shf[lid] : 0.0f;
        v = wsum(v);
        if (lid == 0) bcastf = v;
    }
    __syncthreads();
    const float inv = 1.0f / bcastf;

    for (int i = tid; i < len; i += SOFT_THREADS) out[off + i] *= inv;
}

__global__ void tail_sizes_kernel(const int* __restrict__ sizes, float* __restrict__ out,
                                  int n, int basepos) {
    int i = blockIdx.x * blockDim.x + threadIdx.x;
    if (i < n) out[basepos + i] = (float)sizes[i];
}

// ---------------------------------------------------------------------------
extern "C" void kernel_launch(void* const* d_in, const int* in_sizes, int n_in,
                              void* d_out, int out_size) {
    const float* x   = (const float*)d_in[0];
    const int* sizes = (const int*)d_in[1];
    const float* W1  = (const float*)d_in[2];
    const float* b1  = (const float*)d_in[3];
    const float* W2  = (const float*)d_in[4];
    const float* b2  = (const float*)d_in[5];
    const float* W3  = (const float*)d_in[6];
    const float* b3  = (const float*)d_in[7];
    const float* W4  = (const float*)d_in[8];
    const float* b4  = (const float*)d_in[9];
    float* out = (float*)d_out;

    const int total  = in_sizes[0] / D_IN;
    const int B      = in_sizes[1];
    const int nunits = total / 32;

    cudaFuncSetAttribute(mlp_hmma_kernel, cudaFuncAttributeMaxDynamicSharedMemorySize, SMEM_BYTES);

    mlp_hmma_kernel<<<PERSIST_BLOCKS, THREADS, SMEM_BYTES>>>(x, nunits, W1, b1, W2, b2, W3, b3, W4, b4);
    softmax_seg_kernel<<<B, SOFT_THREADS>>>(sizes, out);

    if (out_size > total) {
        int n = out_size - total;
        tail_sizes_kernel<<<(n + 255) / 256, 256>>>(sizes, out, n, total);
    }
}